// round 3
// baseline (speedup 1.0000x reference)
#include <cuda_runtime.h>
#include <cuda_bf16.h>
#include <math.h>
#include <stdint.h>

// ---------------------------------------------------------------------------
// Problem constants
// ---------------------------------------------------------------------------
#define NB   4        // batch
#define NT   1024     // time steps
#define NL   512      // latent / emb
#define NV   50257    // vocab
#define NR   (NB*NT)  // 4096 rows

// ---------------------------------------------------------------------------
// Scratch (device globals — no allocation allowed)
// ---------------------------------------------------------------------------
__device__ float g_bufA[NR * NL];   // XW0, later H1
__device__ float g_bufB[NR * NL];   // H0
__device__ float g_bufC[NR * NL];   // XW1
__device__ float4 g_hbuf[2][NL];    // double-buffered h state, hT[k] = {h0..h3}
__device__ unsigned g_bar;          // global barrier counter

// ---------------------------------------------------------------------------
// Helpers
// ---------------------------------------------------------------------------
__device__ __forceinline__ unsigned f2tf32(float f) {
    unsigned u;
    asm("cvt.rna.tf32.f32 %0, %1;" : "=r"(u) : "f"(f));
    return u;
}

__device__ __forceinline__ void mma_tf32(float c[4], const unsigned a[4],
                                         const unsigned b[2]) {
    asm volatile(
        "mma.sync.aligned.m16n8k8.row.col.f32.tf32.tf32.f32 "
        "{%0,%1,%2,%3},{%4,%5,%6,%7},{%8,%9},{%0,%1,%2,%3};"
        : "+f"(c[0]), "+f"(c[1]), "+f"(c[2]), "+f"(c[3])
        : "r"(a[0]), "r"(a[1]), "r"(a[2]), "r"(a[3]), "r"(b[0]), "r"(b[1]));
}

// ---------------------------------------------------------------------------
// init: reset barrier counter + zero the h state
// ---------------------------------------------------------------------------
__global__ void init_kernel() {
    const int tid = threadIdx.x;
    if (tid == 0) g_bar = 0u;
    float4 z = make_float4(0.f, 0.f, 0.f, 0.f);
    float4* p = (float4*)g_hbuf;
    for (int i = tid; i < 2 * NL; i += 256) p[i] = z;
}

// ---------------------------------------------------------------------------
// GEMM: C[r][n] = A_row(r) @ B[:, n] + bias[n]
//   A: rows of length 512 (dense r-th row, or gathered via gidx -> embed row)
//   B: 512 x N row-major.  K = 512 fixed, M = 4096 fixed.
//   Tile 128x128x16, tf32 mma.sync m16n8k8, 8 warps (2m x 4n), warp tile 64x32.
// ---------------------------------------------------------------------------
__global__ __launch_bounds__(256, 2)
void gemm_tf32(const float* __restrict__ A, const int* __restrict__ gidx,
               const float* __restrict__ B, const float* __restrict__ bias,
               float* __restrict__ C, int N) {
    __shared__ float As[128][20];   // padded: conflict-free frag loads
    __shared__ float Bs[16][136];   // padded: <=1-way conflict frag loads

    const int tid  = threadIdx.x;
    const int lane = tid & 31;
    const int warp = tid >> 5;
    const int wm = warp & 1;   // 0..1 (M)
    const int wn = warp >> 1;  // 0..3 (N)
    const int g  = lane >> 2;  // 0..7
    const int t4 = lane & 3;   // 0..3

    const int rowBase = blockIdx.y * 128;
    const int nb      = blockIdx.x * 128;

    float acc[4][4][4];
#pragma unroll
    for (int a = 0; a < 4; ++a)
#pragma unroll
        for (int b = 0; b < 4; ++b)
#pragma unroll
            for (int e = 0; e < 4; ++e) acc[a][b][e] = 0.f;

    // Per-thread A load slots (2 x float4): id = tid + i*256
    const int rl0 = tid >> 2;
    const int rl1 = (tid + 256) >> 2;
    const int c4  = tid & 3;
    const float* arow0;
    const float* arow1;
    {
        const int r0 = rowBase + rl0;
        const int r1 = rowBase + rl1;
        arow0 = A + (size_t)(gidx ? gidx[r0] : r0) * NL;
        arow1 = A + (size_t)(gidx ? gidx[r1] : r1) * NL;
    }

    for (int kb = 0; kb < NL; kb += 16) {
        // --- load A tile (float4, coalesced per row) ---
        {
            float4 v0 = *(const float4*)(arow0 + kb + c4 * 4);
            float4 v1 = *(const float4*)(arow1 + kb + c4 * 4);
            float4 w0, w1;
            w0.x = __uint_as_float(f2tf32(v0.x));
            w0.y = __uint_as_float(f2tf32(v0.y));
            w0.z = __uint_as_float(f2tf32(v0.z));
            w0.w = __uint_as_float(f2tf32(v0.w));
            w1.x = __uint_as_float(f2tf32(v1.x));
            w1.y = __uint_as_float(f2tf32(v1.y));
            w1.z = __uint_as_float(f2tf32(v1.z));
            w1.w = __uint_as_float(f2tf32(v1.w));
            *(float4*)&As[rl0][c4 * 4] = w0;
            *(float4*)&As[rl1][c4 * 4] = w1;
        }
        // --- load B tile (scalar: N=50257 is odd, float4 would misalign) ---
#pragma unroll
        for (int i = 0; i < 8; ++i) {
            const int id  = tid + i * 256;
            const int kr  = id >> 7;
            const int col = id & 127;
            const int n   = nb + col;
            float v = (n < N) ? B[(size_t)(kb + kr) * N + n] : 0.f;
            Bs[kr][col] = __uint_as_float(f2tf32(v));
        }
        __syncthreads();

#pragma unroll
        for (int ks = 0; ks < 16; ks += 8) {
            unsigned af[4][4], bf[4][2];
#pragma unroll
            for (int im = 0; im < 4; ++im) {
                const int m0 = wm * 64 + im * 16;
                af[im][0] = __float_as_uint(As[m0 + g    ][ks + t4]);
                af[im][1] = __float_as_uint(As[m0 + g + 8][ks + t4]);
                af[im][2] = __float_as_uint(As[m0 + g    ][ks + t4 + 4]);
                af[im][3] = __float_as_uint(As[m0 + g + 8][ks + t4 + 4]);
            }
#pragma unroll
            for (int in = 0; in < 4; ++in) {
                const int n0 = wn * 32 + in * 8;
                bf[in][0] = __float_as_uint(Bs[ks + t4    ][n0 + g]);
                bf[in][1] = __float_as_uint(Bs[ks + t4 + 4][n0 + g]);
            }
#pragma unroll
            for (int im = 0; im < 4; ++im)
#pragma unroll
                for (int in = 0; in < 4; ++in)
                    mma_tf32(acc[im][in], af[im], bf[in]);
        }
        __syncthreads();
    }

    // --- epilogue: + bias, bounds-guarded scalar stores ---
#pragma unroll
    for (int im = 0; im < 4; ++im) {
        const int r0 = rowBase + wm * 64 + im * 16 + g;
#pragma unroll
        for (int in = 0; in < 4; ++in) {
            const int c0 = nb + wn * 32 + in * 8 + t4 * 2;
#pragma unroll
            for (int e = 0; e < 4; ++e) {
                const int row = r0 + ((e & 2) ? 8 : 0);
                const int col = c0 + (e & 1);
                if (col < N)
                    C[(size_t)row * N + col] = acc[im][in][e] + bias[col];
            }
        }
    }
}

// ---------------------------------------------------------------------------
// RNN scan: for t in [0,1024): h = tanh(A[:,t,:] + h @ Wh); H[:,t,:] = h
//   64 co-resident blocks x 128 threads, software global barrier per step.
//   Block owns 8 output columns j; thread (jl, kq): partial over 32 k for 4 b.
//   h state double-buffered in global, read with ld.cg (L1 is stale-unsafe).
// ---------------------------------------------------------------------------
__global__ __launch_bounds__(128, 1)
void scan_kernel(const float* __restrict__ A, const float* __restrict__ Wh,
                 float* __restrict__ H) {
    __shared__ float4 hT[528];        // padded: index k -> k + (k>>5)
    __shared__ float4 part[16][8];    // [kq][jl]

    const int tid = threadIdx.x;
    const int jl  = tid & 7;
    const int kq  = tid >> 3;         // 0..15
    const int j   = blockIdx.x * 8 + jl;
    const unsigned nblk = gridDim.x;

    const float* wcol = Wh + (size_t)(kq * 32) * NL + j;
    const int hb = kq * 33;           // padded base of this thread's k range

    for (int t = 0; t < NT; ++t) {
        const int buf = t & 1;
        // stage h (written by all blocks last step) into smem, L2-coherent
        for (int i = tid; i < NL; i += 128)
            hT[i + (i >> 5)] = __ldcg(&g_hbuf[buf][i]);
        __syncthreads();

        float ax = 0.f, ay = 0.f, az = 0.f, aw = 0.f;
#pragma unroll 8
        for (int i = 0; i < 32; ++i) {
            const float w = wcol[(size_t)i * NL];
            const float4 hv = hT[hb + i];
            ax = fmaf(w, hv.x, ax);
            ay = fmaf(w, hv.y, ay);
            az = fmaf(w, hv.z, az);
            aw = fmaf(w, hv.w, aw);
        }
        part[kq][jl] = make_float4(ax, ay, az, aw);
        __syncthreads();

        if (tid < 32) {
            const int jj = tid >> 2;
            const int b  = tid & 3;
            float s = 0.f;
#pragma unroll
            for (int q = 0; q < 16; ++q)
                s += ((const float*)&part[q][jj])[b];
            const int jg = blockIdx.x * 8 + jj;
            const size_t off = ((size_t)b * NT + t) * NL + jg;
            const float hn = tanhf(s + A[off]);
            H[off] = hn;
            ((float*)&g_hbuf[buf ^ 1][jg])[b] = hn;
        }
        __threadfence();      // publish h writes (writer threads) before arrive
        __syncthreads();

        if (t < NT - 1) {
            if (tid == 0) {
                atomicAdd(&g_bar, 1u);
                const unsigned tgt = nblk * (unsigned)(t + 1);
                while (*((volatile unsigned*)&g_bar) < tgt) { }
            }
            __syncthreads();
        }
    }
}

// ---------------------------------------------------------------------------
// Launch
// ---------------------------------------------------------------------------
extern "C" void kernel_launch(void* const* d_in, const int* in_sizes, int n_in,
                              void* d_out, int out_size) {
    const int*   x     = (const int*)  d_in[0];  // (4,1024) int32
    const float* embed = (const float*)d_in[1];  // (50257,512)
    const float* Wx0   = (const float*)d_in[2];  // (512,512)
    const float* Wh0   = (const float*)d_in[3];  // (512,512)
    const float* b0    = (const float*)d_in[4];  // (512,)
    const float* Wx1   = (const float*)d_in[5];
    const float* Wh1   = (const float*)d_in[6];
    const float* b1    = (const float*)d_in[7];
    const float* Wu    = (const float*)d_in[8];  // (512,50257)
    const float* bu    = (const float*)d_in[9];  // (50257,)
    float* out = (float*)d_out;                  // (4,1024,50257)

    void *pA = nullptr, *pB = nullptr, *pC = nullptr;
    cudaGetSymbolAddress(&pA, g_bufA);
    cudaGetSymbolAddress(&pB, g_bufB);
    cudaGetSymbolAddress(&pC, g_bufC);
    float* bufA = (float*)pA;
    float* bufB = (float*)pB;
    float* bufC = (float*)pC;

    const dim3 blk(256);
    const dim3 gSmall(NL / 128, NR / 128);              // (4, 32)
    const dim3 gBig((NV + 127) / 128, NR / 128);        // (393, 32)

    // XW0 = embed[x] @ Wx0 + b0
    init_kernel<<<1, 256>>>();
    gemm_tf32<<<gSmall, blk>>>(embed, x, Wx0, b0, bufA, NL);
    // layer 0 scan -> H0
    scan_kernel<<<64, 128>>>(bufA, Wh0, bufB);
    // XW1 = H0 @ Wx1 + b1
    init_kernel<<<1, 256>>>();
    gemm_tf32<<<gSmall, blk>>>(bufB, nullptr, Wx1, b1, bufC, NL);
    // layer 1 scan -> H1 (reuse bufA)
    scan_kernel<<<64, 128>>>(bufC, Wh1, bufA);
    // logits = H1 @ Wu + bu
    gemm_tf32<<<gBig, blk>>>(bufA, nullptr, Wu, bu, out, NV);
}

// round 4
// speedup vs baseline: 1.4064x; 1.4064x over previous
#include <cuda_runtime.h>
#include <cuda_bf16.h>
#include <math.h>
#include <stdint.h>

// ---------------------------------------------------------------------------
// Problem constants
// ---------------------------------------------------------------------------
#define NB   4        // batch
#define NT   1024     // time steps
#define NL   512      // latent / emb
#define NV   50257    // vocab
#define NR   (NB*NT)  // 4096 rows

// GEMM tiling
#define BM   256
#define BN   128
#define BK   16
#define GT   512      // threads per GEMM block
#define GEMM_SMEM ((2*BM*20 + 2*BK*136)*4)   // 58368 bytes

// ---------------------------------------------------------------------------
// Scratch (device globals — no allocation allowed)
// ---------------------------------------------------------------------------
__device__ float g_bufA[NR * NL];   // XW0 (= embed[x]@Wx0 + b0)
__device__ float g_bufB[NR * NL];   // H1 (layer-1 hidden sequence)
__device__ float4 g_h0[2][NL];      // double-buffered layer-0 h, [k] = {b0..b3}
__device__ float4 g_h1[2][NL];      // double-buffered layer-1 h
__device__ unsigned g_bar;          // global barrier counter

// ---------------------------------------------------------------------------
// Helpers
// ---------------------------------------------------------------------------
__device__ __forceinline__ unsigned f2tf32(float f) {
    unsigned u;
    asm("cvt.rna.tf32.f32 %0, %1;" : "=r"(u) : "f"(f));
    return u;
}

__device__ __forceinline__ void mma_tf32(float c[4], const unsigned a[4],
                                         const unsigned b[2]) {
    asm volatile(
        "mma.sync.aligned.m16n8k8.row.col.f32.tf32.tf32.f32 "
        "{%0,%1,%2,%3},{%4,%5,%6,%7},{%8,%9},{%0,%1,%2,%3};"
        : "+f"(c[0]), "+f"(c[1]), "+f"(c[2]), "+f"(c[3])
        : "r"(a[0]), "r"(a[1]), "r"(a[2]), "r"(a[3]), "r"(b[0]), "r"(b[1]));
}

// ---------------------------------------------------------------------------
// init: reset barrier counter + zero both h states
// ---------------------------------------------------------------------------
__global__ void init_kernel() {
    const int tid = threadIdx.x;
    if (tid == 0) g_bar = 0u;
    float4 z = make_float4(0.f, 0.f, 0.f, 0.f);
    for (int i = tid; i < 2 * NL; i += 256) {
        ((float4*)g_h0)[i] = z;
        ((float4*)g_h1)[i] = z;
    }
}

// ---------------------------------------------------------------------------
// GEMM: C[r][n] = A_row(r) @ B[:, n] + bias[n]
//   Tile 256x128x16, tf32 mma.sync m16n8k8, 16 warps (4m x 4n), warp 64x32.
//   Register-staged double buffering: one __syncthreads per k-tile; next
//   tile's global loads issued right after the sync, overlapping the MMAs.
// ---------------------------------------------------------------------------
__global__ __launch_bounds__(GT, 1)
void gemm_tf32(const float* __restrict__ A, const int* __restrict__ gidx,
               const float* __restrict__ B, const float* __restrict__ bias,
               float* __restrict__ C, int N) {
    extern __shared__ float sm[];
    float* As = sm;               // [2][BM][20]   (padded rows)
    float* Bs = sm + 2 * BM * 20; // [2][BK][136]  (padded rows)

    const int tid  = threadIdx.x;
    const int lane = tid & 31;
    const int warp = tid >> 5;
    const int wm = warp & 3;   // 0..3 (M)
    const int wn = warp >> 2;  // 0..3 (N)
    const int g  = lane >> 2;  // 0..7
    const int t4 = lane & 3;   // 0..3

    const int rowBase = blockIdx.y * BM;
    const int nb      = blockIdx.x * BN;

    float acc[4][4][4];
#pragma unroll
    for (int a = 0; a < 4; ++a)
#pragma unroll
        for (int b = 0; b < 4; ++b)
#pragma unroll
            for (int e = 0; e < 4; ++e) acc[a][b][e] = 0.f;

    // A load slots: 2 x float4 per thread (256 rows x 16 k / 512 thr)
    const int rl0 = tid >> 2;          // 0..127
    const int rl1 = rl0 + 128;         // 128..255
    const int c4  = tid & 3;
    const float* arow0;
    const float* arow1;
    {
        const int r0 = rowBase + rl0;
        const int r1 = rowBase + rl1;
        arow0 = A + (size_t)(gidx ? gidx[r0] : r0) * NL;
        arow1 = A + (size_t)(gidx ? gidx[r1] : r1) * NL;
    }

    // ---- prefetch k-tile 0 into registers ----
    float4 pa0, pa1;
    float  pb[4];
    pa0 = *(const float4*)(arow0 + c4 * 4);
    pa1 = *(const float4*)(arow1 + c4 * 4);
#pragma unroll
    for (int i = 0; i < 4; ++i) {
        const int id  = tid + i * GT;
        const int kr  = id >> 7;      // 0..15
        const int col = id & 127;
        const int n   = nb + col;
        pb[i] = (n < N) ? B[(size_t)kr * N + n] : 0.f;
    }

    int w = 0;
    for (int kb = 0; kb < NL; kb += BK) {
        // ---- STS prefetched tile (with rna tf32 conversion) ----
        {
            float4 w0, w1;
            w0.x = __uint_as_float(f2tf32(pa0.x));
            w0.y = __uint_as_float(f2tf32(pa0.y));
            w0.z = __uint_as_float(f2tf32(pa0.z));
            w0.w = __uint_as_float(f2tf32(pa0.w));
            w1.x = __uint_as_float(f2tf32(pa1.x));
            w1.y = __uint_as_float(f2tf32(pa1.y));
            w1.z = __uint_as_float(f2tf32(pa1.z));
            w1.w = __uint_as_float(f2tf32(pa1.w));
            *(float4*)&As[w * (BM * 20) + rl0 * 20 + c4 * 4] = w0;
            *(float4*)&As[w * (BM * 20) + rl1 * 20 + c4 * 4] = w1;
#pragma unroll
            for (int i = 0; i < 4; ++i) {
                const int id  = tid + i * GT;
                const int kr  = id >> 7;
                const int col = id & 127;
                Bs[w * (BK * 136) + kr * 136 + col] =
                    __uint_as_float(f2tf32(pb[i]));
            }
        }
        __syncthreads();

        // ---- issue next tile's global loads (overlaps MMAs below) ----
        if (kb + BK < NL) {
            pa0 = *(const float4*)(arow0 + kb + BK + c4 * 4);
            pa1 = *(const float4*)(arow1 + kb + BK + c4 * 4);
#pragma unroll
            for (int i = 0; i < 4; ++i) {
                const int id  = tid + i * GT;
                const int kr  = id >> 7;
                const int col = id & 127;
                const int n   = nb + col;
                pb[i] = (n < N) ? B[(size_t)(kb + BK + kr) * N + n] : 0.f;
            }
        }

        // ---- MMAs on buffer w ----
        const float* Aw = &As[w * (BM * 20)];
        const float* Bw = &Bs[w * (BK * 136)];
#pragma unroll
        for (int ks = 0; ks < BK; ks += 8) {
            unsigned af[4][4], bf[4][2];
#pragma unroll
            for (int im = 0; im < 4; ++im) {
                const int m0 = wm * 64 + im * 16;
                const float* a0 = Aw + (m0 + g) * 20 + ks + t4;
                const float* a1 = Aw + (m0 + g + 8) * 20 + ks + t4;
                af[im][0] = __float_as_uint(a0[0]);
                af[im][1] = __float_as_uint(a1[0]);
                af[im][2] = __float_as_uint(a0[4]);
                af[im][3] = __float_as_uint(a1[4]);
            }
#pragma unroll
            for (int in = 0; in < 4; ++in) {
                const int n0 = wn * 32 + in * 8;
                bf[in][0] = __float_as_uint(Bw[(ks + t4) * 136 + n0 + g]);
                bf[in][1] = __float_as_uint(Bw[(ks + t4 + 4) * 136 + n0 + g]);
            }
#pragma unroll
            for (int im = 0; im < 4; ++im)
#pragma unroll
                for (int in = 0; in < 4; ++in)
                    mma_tf32(acc[im][in], af[im], bf[in]);
        }
        w ^= 1;   // safe: next STS targets other buffer; the one sync/iter
                  // separates this iter's reads from the write 2 iters later
    }

    // ---- epilogue: + bias, bounds-guarded scalar stores ----
#pragma unroll
    for (int im = 0; im < 4; ++im) {
        const int r0 = rowBase + wm * 64 + im * 16 + g;
#pragma unroll
        for (int in = 0; in < 4; ++in) {
            const int c0 = nb + wn * 32 + in * 8 + t4 * 2;
#pragma unroll
            for (int e = 0; e < 4; ++e) {
                const int row = r0 + ((e & 2) ? 8 : 0);
                const int col = c0 + (e & 1);
                if (col < N)
                    C[(size_t)row * N + col] = acc[im][in][e] + bias[col];
            }
        }
    }
}

// ---------------------------------------------------------------------------
// Fused pipelined RNN scan (both layers in ONE kernel, 1025 epochs).
//   128 blocks: 0..63 -> layer 0, 64..127 -> layer 1 (lagging one step).
//   Epoch e: layer0 computes h0_e = tanh(xw0_e + h0_{e-1}@Wh0)
//            layer1 computes h1_{e-1} = tanh([h0_{e-1};h1_{e-2}]@[Wx1;Wh1]+b1)
//   Both read h buffers [e&1], write [e&1 ^ 1]; global barrier per epoch.
// ---------------------------------------------------------------------------
__global__ __launch_bounds__(128, 1)
void scan_fused(const float* __restrict__ XW0, const float* __restrict__ Wh0,
                const float* __restrict__ Wx1, const float* __restrict__ Wh1,
                const float* __restrict__ b1,  float* __restrict__ H1) {
    __shared__ float4 hT[1056];       // padded: index k -> k + (k>>5)
    __shared__ float4 part[16][8];    // [kq][jl]

    const int tid = threadIdx.x;
    const int jl  = tid & 7;
    const int kq  = tid >> 3;         // 0..15
    const bool lay1 = blockIdx.x >= 64;
    const int blk = lay1 ? blockIdx.x - 64 : blockIdx.x;
    const int j   = blk * 8 + jl;
    const unsigned nblk = gridDim.x;

    // weight column pointer: layer0 spans 32 k's; layer1 spans 64 k's of
    // the stacked [Wx1; Wh1] (kq<8 -> Wx1 rows, kq>=8 -> Wh1 rows)
    const float* wcol;
    if (!lay1) wcol = Wh0 + (size_t)(kq * 32) * NL + j;
    else       wcol = (kq < 8) ? Wx1 + (size_t)(kq * 64) * NL + j
                               : Wh1 + (size_t)((kq - 8) * 64) * NL + j;
    const int hb = lay1 ? kq * 66 : kq * 33;   // padded smem base

    for (int e = 0; e <= NT; ++e) {
        const int buf = e & 1;
        const bool active = lay1 ? (e >= 1) : (e < NT);
        if (active) {
            // stage h state(s) from L2 (must bypass L1 — cross-SM coherence)
            if (!lay1) {
                for (int i = tid; i < NL; i += 128)
                    hT[i + (i >> 5)] = __ldcg(&g_h0[buf][i]);
            } else {
                for (int i = tid; i < NL; i += 128) {
                    hT[i + (i >> 5)] = __ldcg(&g_h0[buf][i]);
                    const int k = NL + i;
                    hT[k + (k >> 5)] = __ldcg(&g_h1[buf][i]);
                }
            }
            __syncthreads();

            float ax = 0.f, ay = 0.f, az = 0.f, aw = 0.f;
            if (!lay1) {
#pragma unroll 8
                for (int i = 0; i < 32; ++i) {
                    const float wv = wcol[(size_t)i * NL];
                    const float4 hv = hT[hb + i];
                    ax = fmaf(wv, hv.x, ax);
                    ay = fmaf(wv, hv.y, ay);
                    az = fmaf(wv, hv.z, az);
                    aw = fmaf(wv, hv.w, aw);
                }
            } else {
#pragma unroll 8
                for (int i = 0; i < 64; ++i) {
                    const float wv = wcol[(size_t)i * NL];
                    const float4 hv = hT[hb + i + (i >> 5)];
                    ax = fmaf(wv, hv.x, ax);
                    ay = fmaf(wv, hv.y, ay);
                    az = fmaf(wv, hv.z, az);
                    aw = fmaf(wv, hv.w, aw);
                }
            }
            part[kq][jl] = make_float4(ax, ay, az, aw);
            __syncthreads();

            if (tid < 32) {
                const int jj = tid >> 2;
                const int b  = tid & 3;
                float s = 0.f;
#pragma unroll
                for (int q = 0; q < 16; ++q)
                    s += ((const float*)&part[q][jj])[b];
                const int jg = blk * 8 + jj;
                if (!lay1) {
                    const size_t off = ((size_t)b * NT + e) * NL + jg;
                    const float hn = tanhf(s + XW0[off]);
                    ((float*)&g_h0[buf ^ 1][jg])[b] = hn;
                } else {
                    const int t = e - 1;
                    const float hn = tanhf(s + b1[jg]);
                    const size_t off = ((size_t)b * NT + t) * NL + jg;
                    H1[off] = hn;
                    ((float*)&g_h1[buf ^ 1][jg])[b] = hn;
                }
            }
        }
        if (e < NT) {
            __threadfence();          // publish h writes before arriving
            __syncthreads();
            if (tid == 0) {
                atomicAdd(&g_bar, 1u);
                const unsigned tgt = nblk * (unsigned)(e + 1);
                while (*((volatile unsigned*)&g_bar) < tgt) { }
            }
            __syncthreads();
        }
    }
}

// ---------------------------------------------------------------------------
// Launch
// ---------------------------------------------------------------------------
extern "C" void kernel_launch(void* const* d_in, const int* in_sizes, int n_in,
                              void* d_out, int out_size) {
    const int*   x     = (const int*)  d_in[0];  // (4,1024) int32
    const float* embed = (const float*)d_in[1];  // (50257,512)
    const float* Wx0   = (const float*)d_in[2];  // (512,512)
    const float* Wh0   = (const float*)d_in[3];  // (512,512)
    const float* b0    = (const float*)d_in[4];  // (512,)
    const float* Wx1   = (const float*)d_in[5];
    const float* Wh1   = (const float*)d_in[6];
    const float* b1    = (const float*)d_in[7];
    const float* Wu    = (const float*)d_in[8];  // (512,50257)
    const float* bu    = (const float*)d_in[9];  // (50257,)
    float* out = (float*)d_out;                  // (4,1024,50257)

    void *pA = nullptr, *pB = nullptr;
    cudaGetSymbolAddress(&pA, g_bufA);
    cudaGetSymbolAddress(&pB, g_bufB);
    float* bufA = (float*)pA;
    float* bufB = (float*)pB;

    // opt-in to >48KB dynamic smem (idempotent; executes immediately)
    cudaFuncSetAttribute(gemm_tf32,
                         cudaFuncAttributeMaxDynamicSharedMemorySize,
                         GEMM_SMEM);

    const dim3 gSmall(NL / BN, NR / BM);             // (4, 16)
    const dim3 gBig((NV + BN - 1) / BN, NR / BM);    // (393, 16)

    // reset barrier + zero h states
    init_kernel<<<1, 256>>>();
    // XW0 = embed[x] @ Wx0 + b0
    gemm_tf32<<<gSmall, GT, GEMM_SMEM>>>(embed, x, Wx0, b0, bufA, NL);
    // fused pipelined scans: layer0 + layer1 -> H1 in bufB
    scan_fused<<<128, 128>>>(bufA, Wh0, Wx1, Wh1, b1, bufB);
    // logits = H1 @ Wu + bu
    gemm_tf32<<<gBig, GT, GEMM_SMEM>>>(bufB, nullptr, Wu, bu, out, NV);
}

// round 5
// speedup vs baseline: 2.1756x; 1.5469x over previous
#include <cuda_runtime.h>
#include <cuda_bf16.h>
#include <math.h>
#include <stdint.h>

// ---------------------------------------------------------------------------
// Problem constants
// ---------------------------------------------------------------------------
#define NB   4        // batch
#define NT   1024     // time steps
#define NL   512      // latent / emb
#define NV   50257    // vocab
#define NR   (NB*NT)  // 4096 rows
#define NVP  50304    // padded vocab pitch (= 393*128, 16B-aligned rows)

// small GEMM tiling (register-staged, R3 kernel)
#define BM   256
#define BN   128
#define BK   16
#define GT   512
#define GEMM_SMEM ((2*BM*20 + 2*BK*136)*4)

// big GEMM tiling (cp.async pipelined)
#define UBM 128
#define UBN 128
#define UBK 16
#define UST 4                      // pipeline stages
#define UAS (UBM*20)               // A stage floats
#define UBS (UBK*132)              // B stage floats
#define UGEMM_SMEM (UST*(UAS+UBS)*4)   // 74752 bytes

// ---------------------------------------------------------------------------
// Scratch (device globals — no allocation allowed)
// ---------------------------------------------------------------------------
__device__ float g_bufA[NR * NL];     // XW0 (= embed[x]@Wx0 + b0)
__device__ float g_bufB[NR * NL];     // H1, stored tf32-rounded
__device__ float g_wu[NL * NVP];      // Wu, tf32-rounded + padded
__device__ float4 g_h0[2][NL];        // double-buffered layer-0 h
__device__ float4 g_h1[2][NL];        // double-buffered layer-1 h
__device__ unsigned g_bar;            // global barrier counter

// ---------------------------------------------------------------------------
// Helpers
// ---------------------------------------------------------------------------
__device__ __forceinline__ unsigned f2tf32(float f) {
    unsigned u;
    asm("cvt.rna.tf32.f32 %0, %1;" : "=r"(u) : "f"(f));
    return u;
}

__device__ __forceinline__ void mma_tf32(float c[4], const unsigned a[4],
                                         const unsigned b[2]) {
    asm volatile(
        "mma.sync.aligned.m16n8k8.row.col.f32.tf32.tf32.f32 "
        "{%0,%1,%2,%3},{%4,%5,%6,%7},{%8,%9},{%0,%1,%2,%3};"
        : "+f"(c[0]), "+f"(c[1]), "+f"(c[2]), "+f"(c[3])
        : "r"(a[0]), "r"(a[1]), "r"(a[2]), "r"(a[3]), "r"(b[0]), "r"(b[1]));
}

__device__ __forceinline__ void cp16(uint32_t dst, const void* src) {
    asm volatile("cp.async.cg.shared.global [%0], [%1], 16;\n"
                 :: "r"(dst), "l"(src));
}

// ---------------------------------------------------------------------------
// init: reset barrier counter + zero both h states
// ---------------------------------------------------------------------------
__global__ void init_kernel() {
    const int tid = threadIdx.x;
    if (tid == 0) g_bar = 0u;
    float4 z = make_float4(0.f, 0.f, 0.f, 0.f);
    for (int i = tid; i < 2 * NL; i += 256) {
        ((float4*)g_h0)[i] = z;
        ((float4*)g_h1)[i] = z;
    }
}

// ---------------------------------------------------------------------------
// Wu prep: g_wu[k][n] = tf32_rna(Wu[k][n]), zero-padded to pitch NVP
// ---------------------------------------------------------------------------
__global__ void wu_prep(const float* __restrict__ Wu) {
    const int n = blockIdx.x * 256 + threadIdx.x;
    const int k = blockIdx.y;
    if (n < NVP)
        g_wu[(size_t)k * NVP + n] =
            (n < NV) ? __uint_as_float(f2tf32(Wu[(size_t)k * NV + n])) : 0.f;
}

// ---------------------------------------------------------------------------
// Small GEMM (R3 kernel): C = A(gathered) @ B + bias, with in-loop tf32 cvt.
// Used only for XW0 (embed gather). Tile 256x128x16, 16 warps.
// ---------------------------------------------------------------------------
__global__ __launch_bounds__(GT, 1)
void gemm_tf32(const float* __restrict__ A, const int* __restrict__ gidx,
               const float* __restrict__ B, const float* __restrict__ bias,
               float* __restrict__ C, int N) {
    extern __shared__ float sm[];
    float* As = sm;
    float* Bs = sm + 2 * BM * 20;

    const int tid  = threadIdx.x;
    const int lane = tid & 31;
    const int warp = tid >> 5;
    const int wm = warp & 3;
    const int wn = warp >> 2;
    const int g  = lane >> 2;
    const int t4 = lane & 3;

    const int rowBase = blockIdx.y * BM;
    const int nb      = blockIdx.x * BN;

    float acc[4][4][4];
#pragma unroll
    for (int a = 0; a < 4; ++a)
#pragma unroll
        for (int b = 0; b < 4; ++b)
#pragma unroll
            for (int e = 0; e < 4; ++e) acc[a][b][e] = 0.f;

    const int rl0 = tid >> 2;
    const int rl1 = rl0 + 128;
    const int c4  = tid & 3;
    const float* arow0;
    const float* arow1;
    {
        const int r0 = rowBase + rl0;
        const int r1 = rowBase + rl1;
        arow0 = A + (size_t)(gidx ? gidx[r0] : r0) * NL;
        arow1 = A + (size_t)(gidx ? gidx[r1] : r1) * NL;
    }

    float4 pa0, pa1;
    float  pb[4];
    pa0 = *(const float4*)(arow0 + c4 * 4);
    pa1 = *(const float4*)(arow1 + c4 * 4);
#pragma unroll
    for (int i = 0; i < 4; ++i) {
        const int id  = tid + i * GT;
        const int kr  = id >> 7;
        const int col = id & 127;
        const int n   = nb + col;
        pb[i] = (n < N) ? B[(size_t)kr * N + n] : 0.f;
    }

    int w = 0;
    for (int kb = 0; kb < NL; kb += BK) {
        {
            float4 w0, w1;
            w0.x = __uint_as_float(f2tf32(pa0.x));
            w0.y = __uint_as_float(f2tf32(pa0.y));
            w0.z = __uint_as_float(f2tf32(pa0.z));
            w0.w = __uint_as_float(f2tf32(pa0.w));
            w1.x = __uint_as_float(f2tf32(pa1.x));
            w1.y = __uint_as_float(f2tf32(pa1.y));
            w1.z = __uint_as_float(f2tf32(pa1.z));
            w1.w = __uint_as_float(f2tf32(pa1.w));
            *(float4*)&As[w * (BM * 20) + rl0 * 20 + c4 * 4] = w0;
            *(float4*)&As[w * (BM * 20) + rl1 * 20 + c4 * 4] = w1;
#pragma unroll
            for (int i = 0; i < 4; ++i) {
                const int id  = tid + i * GT;
                const int kr  = id >> 7;
                const int col = id & 127;
                Bs[w * (BK * 136) + kr * 136 + col] =
                    __uint_as_float(f2tf32(pb[i]));
            }
        }
        __syncthreads();

        if (kb + BK < NL) {
            pa0 = *(const float4*)(arow0 + kb + BK + c4 * 4);
            pa1 = *(const float4*)(arow1 + kb + BK + c4 * 4);
#pragma unroll
            for (int i = 0; i < 4; ++i) {
                const int id  = tid + i * GT;
                const int kr  = id >> 7;
                const int col = id & 127;
                const int n   = nb + col;
                pb[i] = (n < N) ? B[(size_t)(kb + BK + kr) * N + n] : 0.f;
            }
        }

        const float* Aw = &As[w * (BM * 20)];
        const float* Bw = &Bs[w * (BK * 136)];
#pragma unroll
        for (int ks = 0; ks < BK; ks += 8) {
            unsigned af[4][4], bf[4][2];
#pragma unroll
            for (int im = 0; im < 4; ++im) {
                const int m0 = wm * 64 + im * 16;
                const float* a0 = Aw + (m0 + g) * 20 + ks + t4;
                const float* a1 = Aw + (m0 + g + 8) * 20 + ks + t4;
                af[im][0] = __float_as_uint(a0[0]);
                af[im][1] = __float_as_uint(a1[0]);
                af[im][2] = __float_as_uint(a0[4]);
                af[im][3] = __float_as_uint(a1[4]);
            }
#pragma unroll
            for (int in = 0; in < 4; ++in) {
                const int n0 = wn * 32 + in * 8;
                bf[in][0] = __float_as_uint(Bw[(ks + t4) * 136 + n0 + g]);
                bf[in][1] = __float_as_uint(Bw[(ks + t4 + 4) * 136 + n0 + g]);
            }
#pragma unroll
            for (int im = 0; im < 4; ++im)
#pragma unroll
                for (int in = 0; in < 4; ++in)
                    mma_tf32(acc[im][in], af[im], bf[in]);
        }
        w ^= 1;
    }

#pragma unroll
    for (int im = 0; im < 4; ++im) {
        const int r0 = rowBase + wm * 64 + im * 16 + g;
#pragma unroll
        for (int in = 0; in < 4; ++in) {
            const int c0 = nb + wn * 32 + in * 8 + t4 * 2;
#pragma unroll
            for (int e = 0; e < 4; ++e) {
                const int row = r0 + ((e & 2) ? 8 : 0);
                const int col = c0 + (e & 1);
                if (col < N)
                    C[(size_t)row * N + col] = acc[im][in][e] + bias[col];
            }
        }
    }
}

// ---------------------------------------------------------------------------
// Big unembed GEMM: out = H1(tf32 bits) @ g_wu(tf32 bits, pitch NVP) + bu
//   128x128x16 tile, 256 threads (8 warps 2m x 4n, warp 64x32),
//   4-stage cp.async pipeline, ONE __syncthreads per k-tile, no cvt in loop.
// ---------------------------------------------------------------------------
__global__ __launch_bounds__(256, 2)
void gemm_unembed(const float* __restrict__ A, const float* __restrict__ bias,
                  float* __restrict__ C) {
    extern __shared__ float sm[];
    const uint32_t smem_u32 = (uint32_t)__cvta_generic_to_shared(sm);

    const int tid  = threadIdx.x;
    const int lane = tid & 31;
    const int warp = tid >> 5;
    const int wm = warp & 1;   // 0..1
    const int wn = warp >> 1;  // 0..3
    const int g  = lane >> 2;
    const int t4 = lane & 3;

    const int rowBase = blockIdx.y * UBM;
    const int nb      = blockIdx.x * UBN;

    float acc[4][4][4];
#pragma unroll
    for (int a = 0; a < 4; ++a)
#pragma unroll
        for (int b = 0; b < 4; ++b)
#pragma unroll
            for (int e = 0; e < 4; ++e) acc[a][b][e] = 0.f;

    // cp.async slot mapping
    const int arow = tid >> 2;          // A: chunk id = tid, tid+256
    const int ac4  = tid & 3;
    const float* aptr0 = A + (size_t)(rowBase + arow) * NL + ac4 * 4;
    const float* aptr1 = A + (size_t)(rowBase + arow + 64) * NL + ac4 * 4;
    const int bkr0 = tid >> 5;          // B: chunk id = tid, tid+256
    const int bc0  = tid & 31;
    const float* bptr0 = g_wu + (size_t)bkr0 * NVP + nb + bc0 * 4;
    const float* bptr1 = g_wu + (size_t)(bkr0 + 8) * NVP + nb + bc0 * 4;

    const uint32_t adst0 = smem_u32 + (arow * 20 + ac4 * 4) * 4;
    const uint32_t adst1 = smem_u32 + ((arow + 64) * 20 + ac4 * 4) * 4;
    const uint32_t bdst0 = smem_u32 + (UST * UAS + bkr0 * 132 + bc0 * 4) * 4;
    const uint32_t bdst1 = smem_u32 + (UST * UAS + (bkr0 + 8) * 132 + bc0 * 4) * 4;

    const int NKT = NL / UBK;   // 32

    // prologue: fill 3 stages
#pragma unroll
    for (int s = 0; s < UST - 1; ++s) {
        const int kb = s * UBK;
        cp16(adst0 + s * UAS * 4, aptr0 + kb);
        cp16(adst1 + s * UAS * 4, aptr1 + kb);
        cp16(bdst0 + s * UBS * 4, bptr0 + (size_t)kb * NVP);
        cp16(bdst1 + s * UBS * 4, bptr1 + (size_t)kb * NVP);
        asm volatile("cp.async.commit_group;\n" ::);
    }

    for (int kt = 0; kt < NKT; ++kt) {
        asm volatile("cp.async.wait_group 2;\n" ::);
        __syncthreads();

        // issue stage kt+3 (overlaps MMAs below)
        if (kt + UST - 1 < NKT) {
            const int s  = (kt + UST - 1) & (UST - 1);
            const int kb = (kt + UST - 1) * UBK;
            cp16(adst0 + s * UAS * 4, aptr0 + kb);
            cp16(adst1 + s * UAS * 4, aptr1 + kb);
            cp16(bdst0 + s * UBS * 4, bptr0 + (size_t)kb * NVP);
            cp16(bdst1 + s * UBS * 4, bptr1 + (size_t)kb * NVP);
        }
        asm volatile("cp.async.commit_group;\n" ::);

        const float* Aw = sm + (kt & (UST - 1)) * UAS;
        const float* Bw = sm + UST * UAS + (kt & (UST - 1)) * UBS;
#pragma unroll
        for (int ks = 0; ks < UBK; ks += 8) {
            unsigned af[4][4], bf[4][2];
#pragma unroll
            for (int im = 0; im < 4; ++im) {
                const int m0 = wm * 64 + im * 16;
                const float* a0 = Aw + (m0 + g) * 20 + ks + t4;
                const float* a1 = Aw + (m0 + g + 8) * 20 + ks + t4;
                af[im][0] = __float_as_uint(a0[0]);
                af[im][1] = __float_as_uint(a1[0]);
                af[im][2] = __float_as_uint(a0[4]);
                af[im][3] = __float_as_uint(a1[4]);
            }
#pragma unroll
            for (int in = 0; in < 4; ++in) {
                const int n0 = wn * 32 + in * 8;
                bf[in][0] = __float_as_uint(Bw[(ks + t4) * 132 + n0 + g]);
                bf[in][1] = __float_as_uint(Bw[(ks + t4 + 4) * 132 + n0 + g]);
            }
#pragma unroll
            for (int im = 0; im < 4; ++im)
#pragma unroll
                for (int in = 0; in < 4; ++in)
                    mma_tf32(acc[im][in], af[im], bf[in]);
        }
    }

#pragma unroll
    for (int im = 0; im < 4; ++im) {
        const int r0 = rowBase + wm * 64 + im * 16 + g;
#pragma unroll
        for (int in = 0; in < 4; ++in) {
            const int c0 = nb + wn * 32 + in * 8 + t4 * 2;
#pragma unroll
            for (int e = 0; e < 4; ++e) {
                const int row = r0 + ((e & 2) ? 8 : 0);
                const int col = c0 + (e & 1);
                if (col < NV)
                    C[(size_t)row * NV + col] = acc[im][in][e] + bias[col];
            }
        }
    }
}

// ---------------------------------------------------------------------------
// Fused pipelined RNN scan, 256 threads/block, 128 blocks, 1025 epochs.
//   blocks 0..63: layer 0 (h0_e = tanh(xw0_e + h0_{e-1}@Wh0))
//   blocks 64..127: layer 1, one step behind (h1 = tanh([h0;h1]@[Wx1;Wh1]+b1))
//   Weights register-resident; release/acquire global barrier per epoch.
// ---------------------------------------------------------------------------
__global__ __launch_bounds__(256, 1)
void scan_fused(const float* __restrict__ XW0, const float* __restrict__ Wh0,
                const float* __restrict__ Wx1, const float* __restrict__ Wh1,
                const float* __restrict__ b1,  float* __restrict__ H1) {
    __shared__ float4 hT[1088];       // padded: k -> k + (k>>4)
    __shared__ float4 part[32][8];    // [kq][jl]

    const int tid = threadIdx.x;
    const int jl  = tid & 7;
    const int kq  = tid >> 3;         // 0..31
    const bool lay1 = blockIdx.x >= 64;
    const int blk = lay1 ? (int)blockIdx.x - 64 : (int)blockIdx.x;
    const int j   = blk * 8 + jl;

    // ---- preload weight column slice into registers ----
    float wreg[32];
    if (!lay1) {
#pragma unroll
        for (int i = 0; i < 16; ++i)
            wreg[i] = Wh0[(size_t)(kq * 16 + i) * NL + j];
    } else {
#pragma unroll
        for (int i = 0; i < 32; ++i) {
            const int k = kq * 32 + i;
            wreg[i] = (k < NL) ? Wx1[(size_t)k * NL + j]
                               : Wh1[(size_t)(k - NL) * NL + j];
        }
    }

    // writer-thread constants (tid < 32)
    const int jj = tid >> 2;
    const int bb = tid & 3;
    const int jg = blk * 8 + jj;
    const float bias1 = (tid < 32) ? b1[jg] : 0.f;

    unsigned* const barp = &g_bar;

    for (int e = 0; e <= NT; ++e) {
        const int buf = e & 1;
        const bool active = lay1 ? (e >= 1) : (e < NT);

        // early-issue XW0 load for this epoch (independent of h)
        float xw = 0.f;
        if (!lay1 && tid < 32 && e < NT)
            xw = __ldg(&XW0[((size_t)bb * NT + e) * NL + jg]);

        if (active) {
            // stage h state(s) from L2 (bypass L1 — cross-SM coherence)
            if (!lay1) {
                for (int i = tid; i < NL; i += 256)
                    hT[i + (i >> 4)] = __ldcg(&g_h0[buf][i]);
            } else {
                for (int i = tid; i < NL; i += 256) {
                    hT[i + (i >> 4)] = __ldcg(&g_h0[buf][i]);
                    const int k = NL + i;
                    hT[k + (k >> 4)] = __ldcg(&g_h1[buf][i]);
                }
            }
            __syncthreads();

            float ax = 0.f, ay = 0.f, az = 0.f, aw = 0.f;
            if (!lay1) {
                const int hb = kq * 17;
#pragma unroll
                for (int i = 0; i < 16; ++i) {
                    const float4 hv = hT[hb + i];
                    const float wv = wreg[i];
                    ax = fmaf(wv, hv.x, ax);
                    ay = fmaf(wv, hv.y, ay);
                    az = fmaf(wv, hv.z, az);
                    aw = fmaf(wv, hv.w, aw);
                }
            } else {
                const int hb = kq * 34;
#pragma unroll
                for (int i = 0; i < 32; ++i) {
                    const float4 hv = hT[hb + i + (i >> 4)];
                    const float wv = wreg[i];
                    ax = fmaf(wv, hv.x, ax);
                    ay = fmaf(wv, hv.y, ay);
                    az = fmaf(wv, hv.z, az);
                    aw = fmaf(wv, hv.w, aw);
                }
            }
            part[kq][jl] = make_float4(ax, ay, az, aw);
            __syncthreads();

            if (tid < 32) {
                float s = 0.f;
#pragma unroll
                for (int q = 0; q < 32; ++q)
                    s += ((const float*)&part[q][jj])[bb];
                if (!lay1) {
                    const float hn = tanhf(s + xw);
                    __stcg(&((float*)&g_h0[buf ^ 1][jg])[bb], hn);
                } else {
                    const float hn = tanhf(s + bias1);
                    __stcg(&((float*)&g_h1[buf ^ 1][jg])[bb], hn);
                    const size_t off = ((size_t)bb * NT + (e - 1)) * NL + jg;
                    H1[off] = __uint_as_float(f2tf32(hn));   // pre-rounded for GEMM
                }
            }
        }

        if (e < NT) {
            if (tid < 32) __threadfence();   // publish h writes (writers only)
            __syncthreads();
            if (tid == 0) {
                asm volatile("red.release.gpu.global.add.u32 [%0], %1;"
                             :: "l"(barp), "r"(1u) : "memory");
                const unsigned tgt = 128u * (unsigned)(e + 1);
                unsigned v;
                do {
                    asm volatile("ld.acquire.gpu.global.u32 %0, [%1];"
                                 : "=r"(v) : "l"(barp) : "memory");
                } while (v < tgt);
            }
            __syncthreads();
        }
    }
}

// ---------------------------------------------------------------------------
// Launch
// ---------------------------------------------------------------------------
extern "C" void kernel_launch(void* const* d_in, const int* in_sizes, int n_in,
                              void* d_out, int out_size) {
    const int*   x     = (const int*)  d_in[0];
    const float* embed = (const float*)d_in[1];
    const float* Wx0   = (const float*)d_in[2];
    const float* Wh0   = (const float*)d_in[3];
    const float* b0    = (const float*)d_in[4];
    const float* Wx1   = (const float*)d_in[5];
    const float* Wh1   = (const float*)d_in[6];
    const float* b1    = (const float*)d_in[7];
    const float* Wu    = (const float*)d_in[8];
    const float* bu    = (const float*)d_in[9];
    float* out = (float*)d_out;

    void *pA = nullptr, *pB = nullptr;
    cudaGetSymbolAddress(&pA, g_bufA);
    cudaGetSymbolAddress(&pB, g_bufB);
    float* bufA = (float*)pA;
    float* bufB = (float*)pB;

    cudaFuncSetAttribute(gemm_tf32,
                         cudaFuncAttributeMaxDynamicSharedMemorySize,
                         GEMM_SMEM);
    cudaFuncSetAttribute(gemm_unembed,
                         cudaFuncAttributeMaxDynamicSharedMemorySize,
                         UGEMM_SMEM);

    // reset barrier + h states; pre-convert Wu (tf32, padded pitch)
    init_kernel<<<1, 256>>>();
    wu_prep<<<dim3((NVP + 255) / 256, NL), 256>>>(Wu);
    // XW0 = embed[x] @ Wx0 + b0
    const dim3 gSmall(NL / BN, NR / BM);
    gemm_tf32<<<gSmall, GT, GEMM_SMEM>>>(embed, x, Wx0, b0, bufA, NL);
    // fused pipelined scans: layer0 + layer1 -> H1 (tf32-rounded) in bufB
    scan_fused<<<128, 256>>>(bufA, Wh0, Wx1, Wh1, b1, bufB);
    // logits = H1 @ Wu + bu
    const dim3 gBig(NVP / UBN, NR / UBM);   // (393, 32)
    gemm_unembed<<<gBig, 256, UGEMM_SMEM>>>(bufB, bu, out);
}